// round 10
// baseline (speedup 1.0000x reference)
#include <cuda_runtime.h>

#define NN  100000
#define EE  1600000
#define FIN 32
#define HH  128

// ---------------- scratch (static device globals; no allocs) ----------------
__device__ float g_h  [(size_t)NN * HH];
__device__ float g_pre[(size_t)NN * HH];
__device__ float g_agg[(size_t)NN * HH];
__device__ int   g_deg[NN];
__device__ int   g_off[NN + 1];
__device__ int   g_cur[NN];
__device__ int   g_csr[EE];
__device__ int   g_bsum[256];

#define SEL_AGG  0
#define SEL_H    1
#define SEL_PRE  2
#define SEL_EXT  4
#define SEL_NULL 5

__device__ __forceinline__ const float* sel_c(int s, const float* ext) {
    switch (s) {
        case SEL_AGG: return g_agg;
        case SEL_H:   return g_h;
        case SEL_PRE: return g_pre;
        case SEL_EXT: return ext;
        default:      return nullptr;
    }
}
__device__ __forceinline__ float* sel_m(int s, float* ext) {
    switch (s) {
        case SEL_AGG: return g_agg;
        case SEL_H:   return g_h;
        case SEL_PRE: return g_pre;
        case SEL_EXT: return ext;
        default:      return nullptr;
    }
}

__device__ __forceinline__ int edge_at(const void* ei, size_t pos, int i64) {
    if (i64) return (int)((const long long*)ei)[pos];
    return ((const int*)ei)[pos];
}

// ---------------- bf16 split helpers ----------------
// Pack two consecutive floats (even k, odd k) into bf16x2 hi and lo pairs.
__device__ __forceinline__ void split_pair(float e, float o,
                                           unsigned& hp, unsigned& lp) {
    asm("cvt.rn.bf16x2.f32 %0, %1, %2;" : "=r"(hp) : "f"(o), "f"(e));
    float he = __uint_as_float(hp << 16);
    float ho = __uint_as_float(hp & 0xFFFF0000u);
    asm("cvt.rn.bf16x2.f32 %0, %1, %2;" : "=r"(lp) : "f"(o - ho), "f"(e - he));
}

__device__ __forceinline__ void mma16(float* d, const unsigned* a, const unsigned* b) {
    asm("mma.sync.aligned.m16n8k16.row.col.f32.bf16.bf16.f32 "
        "{%0,%1,%2,%3},{%4,%5,%6,%7},{%8,%9},{%0,%1,%2,%3};"
        : "+f"(d[0]), "+f"(d[1]), "+f"(d[2]), "+f"(d[3])
        : "r"(a[0]), "r"(a[1]), "r"(a[2]), "r"(a[3]), "r"(b[0]), "r"(b[1]));
}

// ---------------- CSR build ----------------
__global__ void k_zero_deg() {
    int i = blockIdx.x * blockDim.x + threadIdx.x;
    if (i < NN) g_deg[i] = 0;
}

__global__ void k_count(const void* __restrict__ ei, int i64) {
    int e = blockIdx.x * blockDim.x + threadIdx.x;
    if (e < EE) {
        int dst = edge_at(ei, (size_t)EE + e, i64);
        if ((unsigned)dst < (unsigned)NN)
            atomicAdd(&g_deg[dst], 1);
    }
}

__global__ void k_scan1() {
    __shared__ int s[1024];
    int t = threadIdx.x;
    int i = blockIdx.x * 1024 + t;
    int v = (i < NN) ? g_deg[i] : 0;
    s[t] = v;
    __syncthreads();
    for (int off = 1; off < 1024; off <<= 1) {
        int u = (t >= off) ? s[t - off] : 0;
        __syncthreads();
        s[t] += u;
        __syncthreads();
    }
    if (i < NN) g_off[i + 1] = s[t];
    if (t == 1023) g_bsum[blockIdx.x] = s[1023];
}

__global__ void k_scan2(int nb) {
    __shared__ int s[256];
    int t = threadIdx.x;
    if (t < nb) s[t] = g_bsum[t];
    __syncthreads();
    if (t == 0) {
        int run = 0;
        for (int b = 0; b < nb; b++) { int tmp = s[b]; s[b] = run; run += tmp; }
    }
    __syncthreads();
    if (t < nb) g_bsum[t] = s[t];
}

__global__ void k_scan3() {
    int i = blockIdx.x * blockDim.x + threadIdx.x;
    if (i >= NN) return;
    int v = g_off[i + 1] + g_bsum[i >> 10];
    g_off[i + 1] = v;
    g_cur[i] = v - g_deg[i];
    if (i == 0) g_off[0] = 0;
}

__global__ void k_fill(const void* __restrict__ ei, int i64) {
    int e = blockIdx.x * blockDim.x + threadIdx.x;
    if (e < EE) {
        int src = edge_at(ei, (size_t)e, i64);
        int dst = edge_at(ei, (size_t)EE + e, i64);
        if ((unsigned)dst < (unsigned)NN && (unsigned)src < (unsigned)NN) {
            int pos = atomicAdd(&g_cur[dst], 1);
            if ((unsigned)pos < (unsigned)EE) g_csr[pos] = src;
        }
    }
}

// ---------------- gather / mean-aggregate ----------------
__global__ void k_gather32(const float* __restrict__ x) {
    int idx  = blockIdx.x * blockDim.x + threadIdx.x;
    int node = idx >> 5;
    int lane = idx & 31;
    if (node >= NN) return;
    int beg = g_off[node], end = g_off[node + 1];
    float acc = 0.f;
    #pragma unroll 4
    for (int e = beg; e < end; e++) {
        int s = g_csr[e];
        acc += __ldg(&x[(size_t)s * FIN + lane]);
    }
    float inv = 1.f / fmaxf((float)(end - beg), 1.f);
    g_agg[(size_t)node * FIN + lane] = acc * inv;
}

__global__ void k_gather128() {
    int idx  = blockIdx.x * blockDim.x + threadIdx.x;
    int node = idx >> 5;
    int lane = idx & 31;
    if (node >= NN) return;
    int beg = g_off[node], end = g_off[node + 1];
    const float4* h4 = (const float4*)g_h;
    float4 acc = make_float4(0.f, 0.f, 0.f, 0.f);
    #pragma unroll 4
    for (int e = beg; e < end; e++) {
        int s = g_csr[e];
        float4 v = __ldg(&h4[s * 32 + lane]);
        acc.x += v.x; acc.y += v.y; acc.z += v.z; acc.w += v.w;
    }
    float inv = 1.f / fmaxf((float)(end - beg), 1.f);
    acc.x *= inv; acc.y *= inv; acc.z *= inv; acc.w *= inv;
    ((float4*)g_agg)[node * 32 + lane] = acc;
}

// ---------------- 3-term split-bf16 tensor-core GEMM ----------------
// C[M,128] = [A1 | A2] @ [W1 ; W2] + bias.
// 128x128 C-tile, 256 threads = 8 warps (2M x 4N), warp tile 64x32.
// KC=16 (one k16-step per chunk): smem 18.4KB -> 2 CTAs/SM.
// Term-major mma order (hh x4na, hl x4na, lh x4na) for acc-chain ILP.
#define KC  16
#define KP  8    // k-pairs per chunk
#define PST 9    // packed row stride in u32 (odd => conflict-free)

__global__ __launch_bounds__(256) void k_mma(
    int selA1, int K1,
    int selA2, int K2,
    const float* __restrict__ Aext,
    const float* __restrict__ W1, const float* __restrict__ W2,
    const float* __restrict__ bias,
    int selC, int M)
{
    __shared__ unsigned Ap_hi[128][PST];
    __shared__ unsigned Ap_lo[128][PST];
    __shared__ unsigned Wp_hi[128][PST];   // transposed: [n][k-pair]
    __shared__ unsigned Wp_lo[128][PST];

    const float* A1 = sel_c(selA1, Aext);
    const float* A2 = sel_c(selA2, Aext);
    float* C = sel_m(selC, nullptr);

    int tid  = threadIdx.x;
    int lane = tid & 31;
    int warp = tid >> 5;
    int wm   = (warp >> 2) * 64;
    int wn   = (warp & 3) * 32;
    int m0   = blockIdx.x * 128;

    float acc[4][4][4];
    #pragma unroll
    for (int i = 0; i < 4; i++)
        #pragma unroll
        for (int j = 0; j < 4; j++)
            #pragma unroll
            for (int q = 0; q < 4; q++) acc[i][j][q] = 0.f;

    int Ktot = K1 + K2;
    for (int k0 = 0; k0 < Ktot; k0 += KC) {
        const float* A; const float* W; int lda; int kb;
        if (k0 < K1) { A = A1; W = W1; lda = K1; kb = k0; }
        else         { A = A2; W = W2; lda = K2; kb = k0 - K1; }

        // ---- stage A chunk: 128 rows x 16 k (8 floats per thread) ----
        {
            int row  = tid >> 1;
            int half = tid & 1;          // which 8-k half
            float v[8];
            if (m0 + row < M) {
                const float* ap = &A[(size_t)(m0 + row) * lda + kb + half * 8];
                float4 u0 = *(const float4*)&ap[0];
                float4 u1 = *(const float4*)&ap[4];
                v[0]=u0.x; v[1]=u0.y; v[2]=u0.z; v[3]=u0.w;
                v[4]=u1.x; v[5]=u1.y; v[6]=u1.z; v[7]=u1.w;
            } else {
                #pragma unroll
                for (int i = 0; i < 8; i++) v[i] = 0.f;
            }
            #pragma unroll
            for (int i = 0; i < 4; i++) {
                unsigned hp, lp;
                split_pair(v[2*i], v[2*i+1], hp, lp);
                Ap_hi[row][half * 4 + i] = hp;
                Ap_lo[row][half * 4 + i] = lp;
            }
        }
        // ---- stage W chunk transposed: pairs (k, k+1) per n ----
        {
            int kp = tid >> 5;           // 0..7 (k-pair)
            int n0 = (tid & 31) * 4;
            const float* w0 = &W[(size_t)(kb + 2*kp)     * 128 + n0];
            const float* w1 = &W[(size_t)(kb + 2*kp + 1) * 128 + n0];
            float4 u = *(const float4*)w0;
            float4 t = *(const float4*)w1;
            float a0[4] = {u.x, u.y, u.z, u.w};
            float a1[4] = {t.x, t.y, t.z, t.w};
            #pragma unroll
            for (int i = 0; i < 4; i++) {
                unsigned hp, lp;
                split_pair(a0[i], a1[i], hp, lp);
                Wp_hi[n0 + i][kp] = hp;
                Wp_lo[n0 + i][kp] = lp;
            }
        }
        __syncthreads();

        // ---- compute: one k16 step ----
        {
            int kpb = lane & 3;
            unsigned bh[4][2], bl[4][2];
            #pragma unroll
            for (int na = 0; na < 4; na++) {
                int n = wn + na * 8 + (lane >> 2);
                bh[na][0] = Wp_hi[n][kpb];
                bh[na][1] = Wp_hi[n][kpb + 4];
                bl[na][0] = Wp_lo[n][kpb];
                bl[na][1] = Wp_lo[n][kpb + 4];
            }
            #pragma unroll
            for (int ma = 0; ma < 4; ma++) {
                int r = wm + ma * 16 + (lane >> 2);
                unsigned ah[4], al[4];
                ah[0] = Ap_hi[r    ][kpb];
                ah[1] = Ap_hi[r + 8][kpb];
                ah[2] = Ap_hi[r    ][kpb + 4];
                ah[3] = Ap_hi[r + 8][kpb + 4];
                al[0] = Ap_lo[r    ][kpb];
                al[1] = Ap_lo[r + 8][kpb];
                al[2] = Ap_lo[r    ][kpb + 4];
                al[3] = Ap_lo[r + 8][kpb + 4];
                // term-major: 4 independent accs between same-acc reuses
                #pragma unroll
                for (int na = 0; na < 4; na++) mma16(acc[ma][na], ah, bh[na]);
                #pragma unroll
                for (int na = 0; na < 4; na++) mma16(acc[ma][na], ah, bl[na]);
                #pragma unroll
                for (int na = 0; na < 4; na++) mma16(acc[ma][na], al, bh[na]);
            }
        }
        __syncthreads();
    }

    // ---- epilogue: bias + store ----
    #pragma unroll
    for (int ma = 0; ma < 4; ma++) {
        int m = m0 + wm + ma * 16 + (lane >> 2);
        #pragma unroll
        for (int na = 0; na < 4; na++) {
            int n = wn + na * 8 + (lane & 3) * 2;
            float bx = bias ? bias[n] : 0.f;
            float by = bias ? bias[n + 1] : 0.f;
            if (m < M) {
                float2 v = make_float2(acc[ma][na][0] + bx, acc[ma][na][1] + by);
                *(float2*)&C[(size_t)m * 128 + n] = v;
            }
            if (m + 8 < M) {
                float2 v = make_float2(acc[ma][na][2] + bx, acc[ma][na][3] + by);
                *(float2*)&C[(size_t)(m + 8) * 128 + n] = v;
            }
        }
    }
}

// ---------------- LayerNorm + ReLU + residual (+opt proj, +opt head) --------
__global__ void k_ln(int selRes, const float* __restrict__ xin,
                     const float* __restrict__ Wp,
                     int selOut, float* outExt,
                     const float* __restrict__ g, const float* __restrict__ b,
                     const float* __restrict__ Wh, const float* __restrict__ bh,
                     float* __restrict__ y)
{
    int idx  = blockIdx.x * blockDim.x + threadIdx.x;
    int node = idx >> 5;
    int lane = idx & 31;
    if (node >= NN) return;
    float* out = sel_m(selOut, outExt);

    const float4* p4 = (const float4*)(g_pre + (size_t)node * HH);
    float4 v = p4[lane];
    float s  = v.x + v.y + v.z + v.w;
    float sq = v.x * v.x + v.y * v.y + v.z * v.z + v.w * v.w;
    #pragma unroll
    for (int o = 16; o > 0; o >>= 1) {
        s  += __shfl_xor_sync(0xFFFFFFFFu, s,  o);
        sq += __shfl_xor_sync(0xFFFFFFFFu, sq, o);
    }
    float mu  = s * (1.f / 128.f);
    float var = sq * (1.f / 128.f) - mu * mu;
    float r   = rsqrtf(var + 1e-5f);

    float4 rr;
    if (Wp) {
        float xv = __ldg(&xin[(size_t)node * FIN + lane]);
        rr = make_float4(0.f, 0.f, 0.f, 0.f);
        #pragma unroll
        for (int k = 0; k < FIN; k++) {
            float xk = __shfl_sync(0xFFFFFFFFu, xv, k);
            float4 w = __ldg((const float4*)&Wp[(size_t)k * HH + lane * 4]);
            rr.x = fmaf(xk, w.x, rr.x);
            rr.y = fmaf(xk, w.y, rr.y);
            rr.z = fmaf(xk, w.z, rr.z);
            rr.w = fmaf(xk, w.w, rr.w);
        }
    } else {
        const float* res = sel_c(selRes, nullptr);
        rr = ((const float4*)(res + (size_t)node * HH))[lane];
    }

    float4 gg = ((const float4*)g)[lane];
    float4 bb = ((const float4*)b)[lane];
    float4 o4;
    o4.x = fmaxf((v.x - mu) * r * gg.x + bb.x, 0.f) + rr.x;
    o4.y = fmaxf((v.y - mu) * r * gg.y + bb.y, 0.f) + rr.y;
    o4.z = fmaxf((v.z - mu) * r * gg.z + bb.z, 0.f) + rr.z;
    o4.w = fmaxf((v.w - mu) * r * gg.w + bb.w, 0.f) + rr.w;
    ((float4*)(out + (size_t)node * HH))[lane] = o4;

    if (Wh) {
        float4 w = ((const float4*)Wh)[lane];
        float d = o4.x * w.x + o4.y * w.y + o4.z * w.z + o4.w * w.w;
        #pragma unroll
        for (int o = 16; o > 0; o >>= 1)
            d += __shfl_xor_sync(0xFFFFFFFFu, d, o);
        if (lane == 0) y[node] = d + bh[0];
    }
}

// ---------------- launch ----------------
extern "C" void kernel_launch(void* const* d_in, const int* in_sizes, int n_in,
                              void* d_out, int out_size)
{
    const float* x   = (const float*)d_in[0];
    const void*  ei  = d_in[1];
    int ei64 = (in_sizes[1] == 4 * EE) ? 1 : 0;   // int32 by default (JAX x64 off)

    const float* Wl0 = (const float*)d_in[2];
    const float* bl0 = (const float*)d_in[3];
    const float* Wr0 = (const float*)d_in[4];
    const float* g0  = (const float*)d_in[5];
    const float* be0 = (const float*)d_in[6];
    const float* Wl1 = (const float*)d_in[7];
    const float* bl1 = (const float*)d_in[8];
    const float* Wr1 = (const float*)d_in[9];
    const float* g1  = (const float*)d_in[10];
    const float* be1 = (const float*)d_in[11];
    const float* Wl2 = (const float*)d_in[12];
    const float* bl2 = (const float*)d_in[13];
    const float* Wr2 = (const float*)d_in[14];
    const float* g2  = (const float*)d_in[15];
    const float* be2 = (const float*)d_in[16];
    const float* Wpr = (const float*)d_in[17];
    const float* Wh  = (const float*)d_in[18];
    const float* bh  = (const float*)d_in[19];

    float* out = (float*)d_out;
    bool   big = (out_size >= NN + NN * HH);
    float* yhat   = out;
    float* hout   = big ? (out + NN) : nullptr;
    int    selHF  = big ? SEL_EXT : SEL_H;

    const int T = 256;
    int gridN   = (NN + T - 1) / T;
    int gridE   = (EE + T - 1) / T;
    int gridW   = (NN * 32 + T - 1) / T;
    int nb      = (NN + 1023) / 1024;
    int gridG   = (NN + 127) / 128;

    // ---- CSR build ----
    k_zero_deg<<<gridN, T>>>();
    k_count<<<gridE, T>>>(ei, ei64);
    k_scan1<<<nb, 1024>>>();
    k_scan2<<<1, 256>>>(nb);
    k_scan3<<<gridN, T>>>();
    k_fill<<<gridE, T>>>(ei, ei64);

    // ---- layer 0 (proj residual fused into LN) ----
    k_gather32<<<gridW, T>>>(x);
    k_mma<<<gridG, 256>>>(SEL_AGG, FIN, SEL_EXT, FIN, x, Wl0, Wr0, bl0, SEL_PRE, NN);
    k_ln<<<gridW, T>>>(SEL_NULL, x, Wpr, SEL_H, nullptr, g0, be0, nullptr, nullptr, nullptr);

    // ---- layer 1 ----
    k_gather128<<<gridW, T>>>();
    k_mma<<<gridG, 256>>>(SEL_AGG, HH, SEL_H, HH, nullptr, Wl1, Wr1, bl1, SEL_PRE, NN);
    k_ln<<<gridW, T>>>(SEL_H, nullptr, nullptr, SEL_H, nullptr, g1, be1, nullptr, nullptr, nullptr);

    // ---- layer 2 (head fused into final LN) ----
    k_gather128<<<gridW, T>>>();
    k_mma<<<gridG, 256>>>(SEL_AGG, HH, SEL_H, HH, nullptr, Wl2, Wr2, bl2, SEL_PRE, NN);
    k_ln<<<gridW, T>>>(SEL_H, nullptr, nullptr, selHF, hout, g2, be2, Wh, bh, yhat);
}

// round 16
// speedup vs baseline: 1.0570x; 1.0570x over previous
#include <cuda_runtime.h>
#include <cstdint>
#include <cstddef>

#define NN  100000
#define EE  1600000
#define FIN 32
#define HH  128

// ---------------- scratch (static device globals; no allocs) ----------------
__device__ float g_h  [(size_t)NN * HH];
__device__ float g_pre[(size_t)NN * HH];
__device__ float g_agg[(size_t)NN * HH];
__device__ int   g_deg[NN];
__device__ int   g_off[NN + 1];
__device__ int   g_cur[NN];
__device__ int   g_csr[EE];
__device__ int   g_bsum[256];

#define SEL_AGG  0
#define SEL_H    1
#define SEL_PRE  2
#define SEL_EXT  4
#define SEL_NULL 5

__device__ __forceinline__ const float* sel_c(int s, const float* ext) {
    switch (s) {
        case SEL_AGG: return g_agg;
        case SEL_H:   return g_h;
        case SEL_PRE: return g_pre;
        case SEL_EXT: return ext;
        default:      return nullptr;
    }
}
__device__ __forceinline__ float* sel_m(int s, float* ext) {
    switch (s) {
        case SEL_AGG: return g_agg;
        case SEL_H:   return g_h;
        case SEL_PRE: return g_pre;
        case SEL_EXT: return ext;
        default:      return nullptr;
    }
}

__device__ __forceinline__ int edge_at(const void* ei, size_t pos, int i64) {
    if (i64) return (int)((const long long*)ei)[pos];
    return ((const int*)ei)[pos];
}

// ---------------- fp16 split helpers ----------------
// Pack two consecutive floats (even k, odd k) into f16x2 hi and lo pairs.
// hi = rn_f16(v); lo = rn_f16(v - float(hi)).  ~22 mantissa bits total.
__device__ __forceinline__ void split_pair_f16(float e, float o,
                                               unsigned& hp, unsigned& lp) {
    asm("cvt.rn.f16x2.f32 %0, %1, %2;" : "=r"(hp) : "f"(o), "f"(e));
    float he, ho;
    asm("{ .reg .f16 l, h; mov.b32 {l, h}, %2; cvt.f32.f16 %0, l; cvt.f32.f16 %1, h; }"
        : "=f"(he), "=f"(ho) : "r"(hp));
    asm("cvt.rn.f16x2.f32 %0, %1, %2;" : "=r"(lp) : "f"(o - ho), "f"(e - he));
}
// Single fp16x2 rounding (for weights).
__device__ __forceinline__ unsigned pack_f16(float e, float o) {
    unsigned hp;
    asm("cvt.rn.f16x2.f32 %0, %1, %2;" : "=r"(hp) : "f"(o), "f"(e));
    return hp;
}

__device__ __forceinline__ void mma16(float* d, const unsigned* a, const unsigned* b) {
    asm("mma.sync.aligned.m16n8k16.row.col.f32.f16.f16.f32 "
        "{%0,%1,%2,%3},{%4,%5,%6,%7},{%8,%9},{%0,%1,%2,%3};"
        : "+f"(d[0]), "+f"(d[1]), "+f"(d[2]), "+f"(d[3])
        : "r"(a[0]), "r"(a[1]), "r"(a[2]), "r"(a[3]), "r"(b[0]), "r"(b[1]));
}

// ---------------- CSR build ----------------
__global__ void k_zero_deg() {
    int i = blockIdx.x * blockDim.x + threadIdx.x;
    if (i < NN) g_deg[i] = 0;
}

__global__ void k_count(const void* __restrict__ ei, int i64) {
    int e = blockIdx.x * blockDim.x + threadIdx.x;
    if (e < EE) {
        int dst = edge_at(ei, (size_t)EE + e, i64);
        if ((unsigned)dst < (unsigned)NN)
            atomicAdd(&g_deg[dst], 1);
    }
}

__global__ void k_scan1() {
    __shared__ int s[1024];
    int t = threadIdx.x;
    int i = blockIdx.x * 1024 + t;
    int v = (i < NN) ? g_deg[i] : 0;
    s[t] = v;
    __syncthreads();
    for (int off = 1; off < 1024; off <<= 1) {
        int u = (t >= off) ? s[t - off] : 0;
        __syncthreads();
        s[t] += u;
        __syncthreads();
    }
    if (i < NN) g_off[i + 1] = s[t];
    if (t == 1023) g_bsum[blockIdx.x] = s[1023];
}

__global__ void k_scan2(int nb) {
    __shared__ int s[256];
    int t = threadIdx.x;
    if (t < nb) s[t] = g_bsum[t];
    __syncthreads();
    if (t == 0) {
        int run = 0;
        for (int b = 0; b < nb; b++) { int tmp = s[b]; s[b] = run; run += tmp; }
    }
    __syncthreads();
    if (t < nb) g_bsum[t] = s[t];
}

__global__ void k_scan3() {
    int i = blockIdx.x * blockDim.x + threadIdx.x;
    if (i >= NN) return;
    int v = g_off[i + 1] + g_bsum[i >> 10];
    g_off[i + 1] = v;
    g_cur[i] = v - g_deg[i];
    if (i == 0) g_off[0] = 0;
}

__global__ void k_fill(const void* __restrict__ ei, int i64) {
    int e = blockIdx.x * blockDim.x + threadIdx.x;
    if (e < EE) {
        int src = edge_at(ei, (size_t)e, i64);
        int dst = edge_at(ei, (size_t)EE + e, i64);
        if ((unsigned)dst < (unsigned)NN && (unsigned)src < (unsigned)NN) {
            int pos = atomicAdd(&g_cur[dst], 1);
            if ((unsigned)pos < (unsigned)EE) g_csr[pos] = src;
        }
    }
}

// ---------------- gather / mean-aggregate ----------------
__global__ void k_gather32(const float* __restrict__ x) {
    int idx  = blockIdx.x * blockDim.x + threadIdx.x;
    int node = idx >> 5;
    int lane = idx & 31;
    if (node >= NN) return;
    int beg = g_off[node], end = g_off[node + 1];
    float acc = 0.f;
    #pragma unroll 4
    for (int e = beg; e < end; e++) {
        int s = g_csr[e];
        acc += __ldg(&x[(size_t)s * FIN + lane]);
    }
    float inv = 1.f / fmaxf((float)(end - beg), 1.f);
    g_agg[(size_t)node * FIN + lane] = acc * inv;
}

__global__ void k_gather128() {
    int idx  = blockIdx.x * blockDim.x + threadIdx.x;
    int node = idx >> 5;
    int lane = idx & 31;
    if (node >= NN) return;
    int beg = g_off[node], end = g_off[node + 1];
    const float4* h4 = (const float4*)g_h;
    float4 acc = make_float4(0.f, 0.f, 0.f, 0.f);
    #pragma unroll 4
    for (int e = beg; e < end; e++) {
        int s = g_csr[e];
        float4 v = __ldg(&h4[s * 32 + lane]);
        acc.x += v.x; acc.y += v.y; acc.z += v.z; acc.w += v.w;
    }
    float inv = 1.f / fmaxf((float)(end - beg), 1.f);
    acc.x *= inv; acc.y *= inv; acc.z *= inv; acc.w *= inv;
    ((float4*)g_agg)[node * 32 + lane] = acc;
}

// ---------------- 2-term split-fp16 tensor-core GEMM ----------------
// C[M,128] = [A1 | A2] @ [W1 ; W2] + bias.
// A split into fp16 hi+lo (captures ~22 bits); W rounded to single fp16
// (rel err ~2^-12, dominant).  a*b ~= ah*bh + al*bh : 2 mma per step.
// 128x128 C-tile, 256 threads = 8 warps (2M x 4N), warp tile 64x32.
// KC=16 (one k16-step per chunk).
#define KC  16
#define KP  8    // k-pairs per chunk
#define PST 9    // packed row stride in u32 (odd => conflict-free)

__global__ __launch_bounds__(256) void k_mma(
    int selA1, int K1,
    int selA2, int K2,
    const float* __restrict__ Aext,
    const float* __restrict__ W1, const float* __restrict__ W2,
    const float* __restrict__ bias,
    int selC, int M)
{
    __shared__ unsigned Ap_hi[128][PST];
    __shared__ unsigned Ap_lo[128][PST];
    __shared__ unsigned Wp   [128][PST];   // transposed: [n][k-pair], fp16x2

    const float* A1 = sel_c(selA1, Aext);
    const float* A2 = sel_c(selA2, Aext);
    float* C = sel_m(selC, nullptr);

    int tid  = threadIdx.x;
    int lane = tid & 31;
    int warp = tid >> 5;
    int wm   = (warp >> 2) * 64;
    int wn   = (warp & 3) * 32;
    int m0   = blockIdx.x * 128;

    float acc[4][4][4];
    #pragma unroll
    for (int i = 0; i < 4; i++)
        #pragma unroll
        for (int j = 0; j < 4; j++)
            #pragma unroll
            for (int q = 0; q < 4; q++) acc[i][j][q] = 0.f;

    int Ktot = K1 + K2;
    for (int k0 = 0; k0 < Ktot; k0 += KC) {
        const float* A; const float* W; int lda; int kb;
        if (k0 < K1) { A = A1; W = W1; lda = K1; kb = k0; }
        else         { A = A2; W = W2; lda = K2; kb = k0 - K1; }

        // ---- stage A chunk: 128 rows x 16 k (8 floats per thread) ----
        {
            int row  = tid >> 1;
            int half = tid & 1;          // which 8-k half
            float v[8];
            if (m0 + row < M) {
                const float* ap = &A[(size_t)(m0 + row) * lda + kb + half * 8];
                float4 u0 = *(const float4*)&ap[0];
                float4 u1 = *(const float4*)&ap[4];
                v[0]=u0.x; v[1]=u0.y; v[2]=u0.z; v[3]=u0.w;
                v[4]=u1.x; v[5]=u1.y; v[6]=u1.z; v[7]=u1.w;
            } else {
                #pragma unroll
                for (int i = 0; i < 8; i++) v[i] = 0.f;
            }
            #pragma unroll
            for (int i = 0; i < 4; i++) {
                unsigned hp, lp;
                split_pair_f16(v[2*i], v[2*i+1], hp, lp);
                Ap_hi[row][half * 4 + i] = hp;
                Ap_lo[row][half * 4 + i] = lp;
            }
        }
        // ---- stage W chunk transposed: pairs (k, k+1) per n, single fp16 ----
        {
            int kp = tid >> 5;           // 0..7 (k-pair)
            int n0 = (tid & 31) * 4;
            const float* w0 = &W[(size_t)(kb + 2*kp)     * 128 + n0];
            const float* w1 = &W[(size_t)(kb + 2*kp + 1) * 128 + n0];
            float4 u = *(const float4*)w0;
            float4 t = *(const float4*)w1;
            Wp[n0 + 0][kp] = pack_f16(u.x, t.x);
            Wp[n0 + 1][kp] = pack_f16(u.y, t.y);
            Wp[n0 + 2][kp] = pack_f16(u.z, t.z);
            Wp[n0 + 3][kp] = pack_f16(u.w, t.w);
        }
        __syncthreads();

        // ---- compute: one k16 step, 2 terms ----
        {
            int kpb = lane & 3;
            unsigned bh[4][2];
            #pragma unroll
            for (int na = 0; na < 4; na++) {
                int n = wn + na * 8 + (lane >> 2);
                bh[na][0] = Wp[n][kpb];
                bh[na][1] = Wp[n][kpb + 4];
            }
            #pragma unroll
            for (int ma = 0; ma < 4; ma++) {
                int r = wm + ma * 16 + (lane >> 2);
                unsigned ah[4], al[4];
                ah[0] = Ap_hi[r    ][kpb];
                ah[1] = Ap_hi[r + 8][kpb];
                ah[2] = Ap_hi[r    ][kpb + 4];
                ah[3] = Ap_hi[r + 8][kpb + 4];
                al[0] = Ap_lo[r    ][kpb];
                al[1] = Ap_lo[r + 8][kpb];
                al[2] = Ap_lo[r    ][kpb + 4];
                al[3] = Ap_lo[r + 8][kpb + 4];
                #pragma unroll
                for (int na = 0; na < 4; na++) mma16(acc[ma][na], ah, bh[na]);
                #pragma unroll
                for (int na = 0; na < 4; na++) mma16(acc[ma][na], al, bh[na]);
            }
        }
        __syncthreads();
    }

    // ---- epilogue: bias + store ----
    #pragma unroll
    for (int ma = 0; ma < 4; ma++) {
        int m = m0 + wm + ma * 16 + (lane >> 2);
        #pragma unroll
        for (int na = 0; na < 4; na++) {
            int n = wn + na * 8 + (lane & 3) * 2;
            float bx = bias ? bias[n] : 0.f;
            float by = bias ? bias[n + 1] : 0.f;
            if (m < M) {
                float2 v = make_float2(acc[ma][na][0] + bx, acc[ma][na][1] + by);
                *(float2*)&C[(size_t)m * 128 + n] = v;
            }
            if (m + 8 < M) {
                float2 v = make_float2(acc[ma][na][2] + bx, acc[ma][na][3] + by);
                *(float2*)&C[(size_t)(m + 8) * 128 + n] = v;
            }
        }
    }
}

// ---------------- LayerNorm + ReLU + residual (+opt proj, +opt head) --------
__global__ void k_ln(int selRes, const float* __restrict__ xin,
                     const float* __restrict__ Wp_,
                     int selOut, float* outExt,
                     const float* __restrict__ g, const float* __restrict__ b,
                     const float* __restrict__ Wh, const float* __restrict__ bh,
                     float* __restrict__ y)
{
    int idx  = blockIdx.x * blockDim.x + threadIdx.x;
    int node = idx >> 5;
    int lane = idx & 31;
    if (node >= NN) return;
    float* out = sel_m(selOut, outExt);

    const float4* p4 = (const float4*)(g_pre + (size_t)node * HH);
    float4 v = p4[lane];
    float s  = v.x + v.y + v.z + v.w;
    float sq = v.x * v.x + v.y * v.y + v.z * v.z + v.w * v.w;
    #pragma unroll
    for (int o = 16; o > 0; o >>= 1) {
        s  += __shfl_xor_sync(0xFFFFFFFFu, s,  o);
        sq += __shfl_xor_sync(0xFFFFFFFFu, sq, o);
    }
    float mu  = s * (1.f / 128.f);
    float var = sq * (1.f / 128.f) - mu * mu;
    float r   = rsqrtf(var + 1e-5f);

    float4 rr;
    if (Wp_) {
        float xv = __ldg(&xin[(size_t)node * FIN + lane]);
        rr = make_float4(0.f, 0.f, 0.f, 0.f);
        #pragma unroll
        for (int k = 0; k < FIN; k++) {
            float xk = __shfl_sync(0xFFFFFFFFu, xv, k);
            float4 w = __ldg((const float4*)&Wp_[(size_t)k * HH + lane * 4]);
            rr.x = fmaf(xk, w.x, rr.x);
            rr.y = fmaf(xk, w.y, rr.y);
            rr.z = fmaf(xk, w.z, rr.z);
            rr.w = fmaf(xk, w.w, rr.w);
        }
    } else {
        const float* res = sel_c(selRes, nullptr);
        rr = ((const float4*)(res + (size_t)node * HH))[lane];
    }

    float4 gg = ((const float4*)g)[lane];
    float4 bb = ((const float4*)b)[lane];
    float4 o4;
    o4.x = fmaxf((v.x - mu) * r * gg.x + bb.x, 0.f) + rr.x;
    o4.y = fmaxf((v.y - mu) * r * gg.y + bb.y, 0.f) + rr.y;
    o4.z = fmaxf((v.z - mu) * r * gg.z + bb.z, 0.f) + rr.z;
    o4.w = fmaxf((v.w - mu) * r * gg.w + bb.w, 0.f) + rr.w;
    ((float4*)(out + (size_t)node * HH))[lane] = o4;

    if (Wh) {
        float4 w = ((const float4*)Wh)[lane];
        float d = o4.x * w.x + o4.y * w.y + o4.z * w.z + o4.w * w.w;
        #pragma unroll
        for (int o = 16; o > 0; o >>= 1)
            d += __shfl_xor_sync(0xFFFFFFFFu, d, o);
        if (lane == 0) y[node] = d + bh[0];
    }
}

// ---------------- launch ----------------
extern "C" void kernel_launch(void* const* d_in, const int* in_sizes, int n_in,
                              void* d_out, int out_size)
{
    const float* x   = (const float*)d_in[0];
    const void*  ei  = d_in[1];
    int ei64 = (in_sizes[1] == 4 * EE) ? 1 : 0;   // int32 by default (JAX x64 off)

    const float* Wl0 = (const float*)d_in[2];
    const float* bl0 = (const float*)d_in[3];
    const float* Wr0 = (const float*)d_in[4];
    const float* g0  = (const float*)d_in[5];
    const float* be0 = (const float*)d_in[6];
    const float* Wl1 = (const float*)d_in[7];
    const float* bl1 = (const float*)d_in[8];
    const float* Wr1 = (const float*)d_in[9];
    const float* g1  = (const float*)d_in[10];
    const float* be1 = (const float*)d_in[11];
    const float* Wl2 = (const float*)d_in[12];
    const float* bl2 = (const float*)d_in[13];
    const float* Wr2 = (const float*)d_in[14];
    const float* g2  = (const float*)d_in[15];
    const float* be2 = (const float*)d_in[16];
    const float* Wpr = (const float*)d_in[17];
    const float* Wh  = (const float*)d_in[18];
    const float* bh  = (const float*)d_in[19];

    float* out = (float*)d_out;
    bool   big = (out_size >= NN + NN * HH);
    float* yhat   = out;
    float* hout   = big ? (out + NN) : nullptr;
    int    selHF  = big ? SEL_EXT : SEL_H;

    const int T = 256;
    int gridN   = (NN + T - 1) / T;
    int gridE   = (EE + T - 1) / T;
    int gridW   = (NN * 32 + T - 1) / T;
    int nb      = (NN + 1023) / 1024;
    int gridG   = (NN + 127) / 128;

    // ---- CSR build ----
    k_zero_deg<<<gridN, T>>>();
    k_count<<<gridE, T>>>(ei, ei64);
    k_scan1<<<nb, 1024>>>();
    k_scan2<<<1, 256>>>(nb);
    k_scan3<<<gridN, T>>>();
    k_fill<<<gridE, T>>>(ei, ei64);

    // ---- layer 0 (proj residual fused into LN) ----
    k_gather32<<<gridW, T>>>(x);
    k_mma<<<gridG, 256>>>(SEL_AGG, FIN, SEL_EXT, FIN, x, Wl0, Wr0, bl0, SEL_PRE, NN);
    k_ln<<<gridW, T>>>(SEL_NULL, x, Wpr, SEL_H, nullptr, g0, be0, nullptr, nullptr, nullptr);

    // ---- layer 1 ----
    k_gather128<<<gridW, T>>>();
    k_mma<<<gridG, 256>>>(SEL_AGG, HH, SEL_H, HH, nullptr, Wl1, Wr1, bl1, SEL_PRE, NN);
    k_ln<<<gridW, T>>>(SEL_H, nullptr, nullptr, SEL_H, nullptr, g1, be1, nullptr, nullptr, nullptr);

    // ---- layer 2 (head fused into final LN) ----
    k_gather128<<<gridW, T>>>();
    k_mma<<<gridG, 256>>>(SEL_AGG, HH, SEL_H, HH, nullptr, Wl2, Wr2, bl2, SEL_PRE, NN);
    k_ln<<<gridW, T>>>(SEL_H, nullptr, nullptr, selHF, hout, g2, be2, Wh, bh, yhat);
}

// round 17
// speedup vs baseline: 1.0731x; 1.0152x over previous
#include <cuda_runtime.h>
#include <cstdint>
#include <cstddef>

#define NN  100000
#define EE  1600000
#define FIN 32
#define HH  128

// ---------------- scratch (static device globals; no allocs) ----------------
__device__ float g_h  [(size_t)NN * HH];
__device__ float g_pre[(size_t)NN * HH];
__device__ float g_agg[(size_t)NN * HH];
__device__ int   g_deg[NN];
__device__ int   g_off[NN + 1];
__device__ int   g_cur[NN];
__device__ int   g_csr[EE];
__device__ int   g_bsum[256];

#define SEL_AGG  0
#define SEL_H    1
#define SEL_PRE  2
#define SEL_EXT  4
#define SEL_NULL 5

__device__ __forceinline__ const float* sel_c(int s, const float* ext) {
    switch (s) {
        case SEL_AGG: return g_agg;
        case SEL_H:   return g_h;
        case SEL_PRE: return g_pre;
        case SEL_EXT: return ext;
        default:      return nullptr;
    }
}
__device__ __forceinline__ float* sel_m(int s, float* ext) {
    switch (s) {
        case SEL_AGG: return g_agg;
        case SEL_H:   return g_h;
        case SEL_PRE: return g_pre;
        case SEL_EXT: return ext;
        default:      return nullptr;
    }
}

__device__ __forceinline__ int edge_at(const void* ei, size_t pos, int i64) {
    if (i64) return (int)((const long long*)ei)[pos];
    return ((const int*)ei)[pos];
}

// ---------------- fp16 split helpers ----------------
// Pack two consecutive floats (even k, odd k) into f16x2 hi and lo pairs.
__device__ __forceinline__ void split_pair_f16(float e, float o,
                                               unsigned& hp, unsigned& lp) {
    asm("cvt.rn.f16x2.f32 %0, %1, %2;" : "=r"(hp) : "f"(o), "f"(e));
    float he, ho;
    asm("{ .reg .f16 l, h; mov.b32 {l, h}, %2; cvt.f32.f16 %0, l; cvt.f32.f16 %1, h; }"
        : "=f"(he), "=f"(ho) : "r"(hp));
    asm("cvt.rn.f16x2.f32 %0, %1, %2;" : "=r"(lp) : "f"(o - ho), "f"(e - he));
}
__device__ __forceinline__ unsigned pack_f16(float e, float o) {
    unsigned hp;
    asm("cvt.rn.f16x2.f32 %0, %1, %2;" : "=r"(hp) : "f"(o), "f"(e));
    return hp;
}

__device__ __forceinline__ void mma16(float* d, const unsigned* a, const unsigned* b) {
    asm("mma.sync.aligned.m16n8k16.row.col.f32.f16.f16.f32 "
        "{%0,%1,%2,%3},{%4,%5,%6,%7},{%8,%9},{%0,%1,%2,%3};"
        : "+f"(d[0]), "+f"(d[1]), "+f"(d[2]), "+f"(d[3])
        : "r"(a[0]), "r"(a[1]), "r"(a[2]), "r"(a[3]), "r"(b[0]), "r"(b[1]));
}

// ---------------- CSR build ----------------
__global__ void k_zero_deg() {
    int i = blockIdx.x * blockDim.x + threadIdx.x;
    if (i < NN) g_deg[i] = 0;
}

__global__ void k_count(const void* __restrict__ ei, int i64) {
    int e = blockIdx.x * blockDim.x + threadIdx.x;
    if (e < EE) {
        int dst = edge_at(ei, (size_t)EE + e, i64);
        if ((unsigned)dst < (unsigned)NN)
            atomicAdd(&g_deg[dst], 1);
    }
}

__global__ void k_scan1() {
    __shared__ int s[1024];
    int t = threadIdx.x;
    int i = blockIdx.x * 1024 + t;
    int v = (i < NN) ? g_deg[i] : 0;
    s[t] = v;
    __syncthreads();
    for (int off = 1; off < 1024; off <<= 1) {
        int u = (t >= off) ? s[t - off] : 0;
        __syncthreads();
        s[t] += u;
        __syncthreads();
    }
    if (i < NN) g_off[i + 1] = s[t];
    if (t == 1023) g_bsum[blockIdx.x] = s[1023];
}

// scan3 with scan2 fused: every block redoes the small block-sum prefix scan
__global__ void k_scan3() {
    __shared__ int s[256];
    const int nb = (NN + 1023) >> 10;   // 98
    int t = threadIdx.x;
    int orig = (t < nb) ? g_bsum[t] : 0;
    s[t] = orig;
    __syncthreads();
    for (int off = 1; off < 256; off <<= 1) {
        int u = (t >= off) ? s[t - off] : 0;
        __syncthreads();
        s[t] += u;
        __syncthreads();
    }
    int excl = s[t] - orig;
    __syncthreads();
    s[t] = excl;
    __syncthreads();
    int i = blockIdx.x * blockDim.x + t;
    if (i < NN) {
        int v = g_off[i + 1] + s[i >> 10];
        g_off[i + 1] = v;
        g_cur[i] = v - g_deg[i];
        if (i == 0) g_off[0] = 0;
    }
}

__global__ void k_fill(const void* __restrict__ ei, int i64) {
    int e = blockIdx.x * blockDim.x + threadIdx.x;
    if (e < EE) {
        int src = edge_at(ei, (size_t)e, i64);
        int dst = edge_at(ei, (size_t)EE + e, i64);
        if ((unsigned)dst < (unsigned)NN && (unsigned)src < (unsigned)NN) {
            int pos = atomicAdd(&g_cur[dst], 1);
            if ((unsigned)pos < (unsigned)EE) g_csr[pos] = src;
        }
    }
}

// ---------------- gather / mean-aggregate ----------------
__global__ void k_gather32(const float* __restrict__ x) {
    int idx  = blockIdx.x * blockDim.x + threadIdx.x;
    int node = idx >> 5;
    int lane = idx & 31;
    if (node >= NN) return;
    int beg = g_off[node], end = g_off[node + 1];
    float acc = 0.f;
    #pragma unroll 4
    for (int e = beg; e < end; e++) {
        int s = g_csr[e];
        acc += __ldg(&x[(size_t)s * FIN + lane]);
    }
    float inv = 1.f / fmaxf((float)(end - beg), 1.f);
    g_agg[(size_t)node * FIN + lane] = acc * inv;
}

__global__ void k_gather128() {
    int idx  = blockIdx.x * blockDim.x + threadIdx.x;
    int node = idx >> 5;
    int lane = idx & 31;
    if (node >= NN) return;
    int beg = g_off[node], end = g_off[node + 1];
    const float4* h4 = (const float4*)g_h;
    float4 acc = make_float4(0.f, 0.f, 0.f, 0.f);
    #pragma unroll 4
    for (int e = beg; e < end; e++) {
        int s = g_csr[e];
        float4 v = __ldg(&h4[s * 32 + lane]);
        acc.x += v.x; acc.y += v.y; acc.z += v.z; acc.w += v.w;
    }
    float inv = 1.f / fmaxf((float)(end - beg), 1.f);
    acc.x *= inv; acc.y *= inv; acc.z *= inv; acc.w *= inv;
    ((float4*)g_agg)[node * 32 + lane] = acc;
}

// ---------------- 2-term split-fp16 tensor-core GEMM, KC=32 ----------------
// C[M,128] = [A1 | A2] @ [W1 ; W2] + bias.
// A split into fp16 hi+lo; W single fp16.  a*b ~= ah*bh + al*bh.
// 128x128 C-tile, 256 threads = 8 warps (2M x 4N), warp tile 64x32.
// KC=32 (two k16-steps per chunk) -> 8 chunks for K=256.
#define KC  32
#define PST 17   // packed row stride in u32 (odd => conflict-free); 16 k-pairs used

__global__ __launch_bounds__(256) void k_mma(
    int selA1, int K1,
    int selA2, int K2,
    const float* __restrict__ Aext,
    const float* __restrict__ W1, const float* __restrict__ W2,
    const float* __restrict__ bias,
    int selC, int M)
{
    __shared__ unsigned Ap_hi[128][PST];
    __shared__ unsigned Ap_lo[128][PST];
    __shared__ unsigned Wp   [128][PST];   // transposed: [n][k-pair], fp16x2

    const float* A1 = sel_c(selA1, Aext);
    const float* A2 = sel_c(selA2, Aext);
    float* C = sel_m(selC, nullptr);

    int tid  = threadIdx.x;
    int lane = tid & 31;
    int warp = tid >> 5;
    int wm   = (warp >> 2) * 64;
    int wn   = (warp & 3) * 32;
    int m0   = blockIdx.x * 128;

    float acc[4][4][4];
    #pragma unroll
    for (int i = 0; i < 4; i++)
        #pragma unroll
        for (int j = 0; j < 4; j++)
            #pragma unroll
            for (int q = 0; q < 4; q++) acc[i][j][q] = 0.f;

    int Ktot = K1 + K2;
    for (int k0 = 0; k0 < Ktot; k0 += KC) {
        // K1 is a multiple of 32 in all call sites -> chunk never crosses A1/A2
        const float* A; const float* W; int lda; int kb;
        if (k0 < K1) { A = A1; W = W1; lda = K1; kb = k0; }
        else         { A = A2; W = W2; lda = K2; kb = k0 - K1; }

        // ---- stage A chunk: 128 rows x 32 k (16 floats per thread) ----
        {
            int row  = tid >> 1;
            int half = tid & 1;          // which 16-k half
            float v[16];
            if (m0 + row < M) {
                const float* ap = &A[(size_t)(m0 + row) * lda + kb + half * 16];
                #pragma unroll
                for (int q = 0; q < 4; q++) {
                    float4 u = *(const float4*)&ap[q * 4];
                    v[q*4+0]=u.x; v[q*4+1]=u.y; v[q*4+2]=u.z; v[q*4+3]=u.w;
                }
            } else {
                #pragma unroll
                for (int i = 0; i < 16; i++) v[i] = 0.f;
            }
            #pragma unroll
            for (int i = 0; i < 8; i++) {
                unsigned hp, lp;
                split_pair_f16(v[2*i], v[2*i+1], hp, lp);
                Ap_hi[row][half * 8 + i] = hp;
                Ap_lo[row][half * 8 + i] = lp;
            }
        }
        // ---- stage W chunk transposed: 16 k-pairs x 128 n, single fp16 ----
        {
            int kp = tid >> 4;           // 0..15 (k-pair)
            int n0 = (tid & 15) * 8;
            const float* w0 = &W[(size_t)(kb + 2*kp)     * 128 + n0];
            const float* w1 = &W[(size_t)(kb + 2*kp + 1) * 128 + n0];
            float a0[8], a1[8];
            #pragma unroll
            for (int q = 0; q < 2; q++) {
                float4 u = *(const float4*)&w0[q * 4];
                a0[q*4+0]=u.x; a0[q*4+1]=u.y; a0[q*4+2]=u.z; a0[q*4+3]=u.w;
                float4 t = *(const float4*)&w1[q * 4];
                a1[q*4+0]=t.x; a1[q*4+1]=t.y; a1[q*4+2]=t.z; a1[q*4+3]=t.w;
            }
            #pragma unroll
            for (int i = 0; i < 8; i++)
                Wp[n0 + i][kp] = pack_f16(a0[i], a1[i]);
        }
        __syncthreads();

        // ---- compute: 2 k16-steps, 2 terms each ----
        #pragma unroll
        for (int ks2 = 0; ks2 < 2; ks2++) {
            int kpb = ks2 * 8 + (lane & 3);
            unsigned bh[4][2];
            #pragma unroll
            for (int na = 0; na < 4; na++) {
                int n = wn + na * 8 + (lane >> 2);
                bh[na][0] = Wp[n][kpb];
                bh[na][1] = Wp[n][kpb + 4];
            }
            #pragma unroll
            for (int ma = 0; ma < 4; ma++) {
                int r = wm + ma * 16 + (lane >> 2);
                unsigned ah[4], al[4];
                ah[0] = Ap_hi[r    ][kpb];
                ah[1] = Ap_hi[r + 8][kpb];
                ah[2] = Ap_hi[r    ][kpb + 4];
                ah[3] = Ap_hi[r + 8][kpb + 4];
                al[0] = Ap_lo[r    ][kpb];
                al[1] = Ap_lo[r + 8][kpb];
                al[2] = Ap_lo[r    ][kpb + 4];
                al[3] = Ap_lo[r + 8][kpb + 4];
                #pragma unroll
                for (int na = 0; na < 4; na++) mma16(acc[ma][na], ah, bh[na]);
                #pragma unroll
                for (int na = 0; na < 4; na++) mma16(acc[ma][na], al, bh[na]);
            }
        }
        __syncthreads();
    }

    // ---- epilogue: bias + store ----
    #pragma unroll
    for (int ma = 0; ma < 4; ma++) {
        int m = m0 + wm + ma * 16 + (lane >> 2);
        #pragma unroll
        for (int na = 0; na < 4; na++) {
            int n = wn + na * 8 + (lane & 3) * 2;
            float bx = bias ? bias[n] : 0.f;
            float by = bias ? bias[n + 1] : 0.f;
            if (m < M) {
                float2 v = make_float2(acc[ma][na][0] + bx, acc[ma][na][1] + by);
                *(float2*)&C[(size_t)m * 128 + n] = v;
            }
            if (m + 8 < M) {
                float2 v = make_float2(acc[ma][na][2] + bx, acc[ma][na][3] + by);
                *(float2*)&C[(size_t)(m + 8) * 128 + n] = v;
            }
        }
    }
}

// ---------------- LayerNorm + ReLU + residual (+opt proj, +opt head) --------
__global__ void k_ln(int selRes, const float* __restrict__ xin,
                     const float* __restrict__ Wp_,
                     int selOut, float* outExt,
                     const float* __restrict__ g, const float* __restrict__ b,
                     const float* __restrict__ Wh, const float* __restrict__ bh,
                     float* __restrict__ y)
{
    int idx  = blockIdx.x * blockDim.x + threadIdx.x;
    int node = idx >> 5;
    int lane = idx & 31;
    if (node >= NN) return;
    float* out = sel_m(selOut, outExt);

    const float4* p4 = (const float4*)(g_pre + (size_t)node * HH);
    float4 v = p4[lane];
    float s  = v.x + v.y + v.z + v.w;
    float sq = v.x * v.x + v.y * v.y + v.z * v.z + v.w * v.w;
    #pragma unroll
    for (int o = 16; o > 0; o >>= 1) {
        s  += __shfl_xor_sync(0xFFFFFFFFu, s,  o);
        sq += __shfl_xor_sync(0xFFFFFFFFu, sq, o);
    }
    float mu  = s * (1.f / 128.f);
    float var = sq * (1.f / 128.f) - mu * mu;
    float r   = rsqrtf(var + 1e-5f);

    float4 rr;
    if (Wp_) {
        float xv = __ldg(&xin[(size_t)node * FIN + lane]);
        rr = make_float4(0.f, 0.f, 0.f, 0.f);
        #pragma unroll
        for (int k = 0; k < FIN; k++) {
            float xk = __shfl_sync(0xFFFFFFFFu, xv, k);
            float4 w = __ldg((const float4*)&Wp_[(size_t)k * HH + lane * 4]);
            rr.x = fmaf(xk, w.x, rr.x);
            rr.y = fmaf(xk, w.y, rr.y);
            rr.z = fmaf(xk, w.z, rr.z);
            rr.w = fmaf(xk, w.w, rr.w);
        }
    } else {
        const float* res = sel_c(selRes, nullptr);
        rr = ((const float4*)(res + (size_t)node * HH))[lane];
    }

    float4 gg = ((const float4*)g)[lane];
    float4 bb = ((const float4*)b)[lane];
    float4 o4;
    o4.x = fmaxf((v.x - mu) * r * gg.x + bb.x, 0.f) + rr.x;
    o4.y = fmaxf((v.y - mu) * r * gg.y + bb.y, 0.f) + rr.y;
    o4.z = fmaxf((v.z - mu) * r * gg.z + bb.z, 0.f) + rr.z;
    o4.w = fmaxf((v.w - mu) * r * gg.w + bb.w, 0.f) + rr.w;
    ((float4*)(out + (size_t)node * HH))[lane] = o4;

    if (Wh) {
        float4 w = ((const float4*)Wh)[lane];
        float d = o4.x * w.x + o4.y * w.y + o4.z * w.z + o4.w * w.w;
        #pragma unroll
        for (int o = 16; o > 0; o >>= 1)
            d += __shfl_xor_sync(0xFFFFFFFFu, d, o);
        if (lane == 0) y[node] = d + bh[0];
    }
}

// ---------------- launch ----------------
extern "C" void kernel_launch(void* const* d_in, const int* in_sizes, int n_in,
                              void* d_out, int out_size)
{
    const float* x   = (const float*)d_in[0];
    const void*  ei  = d_in[1];
    int ei64 = (in_sizes[1] == 4 * EE) ? 1 : 0;   // int32 by default (JAX x64 off)

    const float* Wl0 = (const float*)d_in[2];
    const float* bl0 = (const float*)d_in[3];
    const float* Wr0 = (const float*)d_in[4];
    const float* g0  = (const float*)d_in[5];
    const float* be0 = (const float*)d_in[6];
    const float* Wl1 = (const float*)d_in[7];
    const float* bl1 = (const float*)d_in[8];
    const float* Wr1 = (const float*)d_in[9];
    const float* g1  = (const float*)d_in[10];
    const float* be1 = (const float*)d_in[11];
    const float* Wl2 = (const float*)d_in[12];
    const float* bl2 = (const float*)d_in[13];
    const float* Wr2 = (const float*)d_in[14];
    const float* g2  = (const float*)d_in[15];
    const float* be2 = (const float*)d_in[16];
    const float* Wpr = (const float*)d_in[17];
    const float* Wh  = (const float*)d_in[18];
    const float* bh  = (const float*)d_in[19];

    float* out = (float*)d_out;
    bool   big = (out_size >= NN + NN * HH);
    float* yhat   = out;
    float* hout   = big ? (out + NN) : nullptr;
    int    selHF  = big ? SEL_EXT : SEL_H;

    const int T = 256;
    int gridN   = (NN + T - 1) / T;
    int gridE   = (EE + T - 1) / T;
    int gridW   = (NN * 32 + T - 1) / T;
    int nb      = (NN + 1023) / 1024;
    int gridG   = (NN + 127) / 128;

    // ---- CSR build (scan2 fused into scan3) ----
    k_zero_deg<<<gridN, T>>>();
    k_count<<<gridE, T>>>(ei, ei64);
    k_scan1<<<nb, 1024>>>();
    k_scan3<<<gridN, T>>>();
    k_fill<<<gridE, T>>>(ei, ei64);

    // ---- layer 0 (proj residual fused into LN) ----
    k_gather32<<<gridW, T>>>(x);
    k_mma<<<gridG, 256>>>(SEL_AGG, FIN, SEL_EXT, FIN, x, Wl0, Wr0, bl0, SEL_PRE, NN);
    k_ln<<<gridW, T>>>(SEL_NULL, x, Wpr, SEL_H, nullptr, g0, be0, nullptr, nullptr, nullptr);

    // ---- layer 1 ----
    k_gather128<<<gridW, T>>>();
    k_mma<<<gridG, 256>>>(SEL_AGG, HH, SEL_H, HH, nullptr, Wl1, Wr1, bl1, SEL_PRE, NN);
    k_ln<<<gridW, T>>>(SEL_H, nullptr, nullptr, SEL_H, nullptr, g1, be1, nullptr, nullptr, nullptr);

    // ---- layer 2 (head fused into final LN) ----
    k_gather128<<<gridW, T>>>();
    k_mma<<<gridG, 256>>>(SEL_AGG, HH, SEL_H, HH, nullptr, Wl2, Wr2, bl2, SEL_PRE, NN);
    k_ln<<<gridW, T>>>(SEL_H, nullptr, nullptr, selHF, hout, g2, be2, Wh, bh, yhat);
}